// round 15
// baseline (speedup 1.0000x reference)
#include <cuda_runtime.h>
#include <cuda_fp16.h>
#include <cstdint>

// Problem constants
#define NRES 8192
#define HALF_N 4096
#define KNBR 32
#define DMODEL 768
#define CPAIR 128
#define NHEAD 8
#define SDIM 64
#define PPTS 8
#define NPTS 24            // 3*P
#define QKV_W 1536         // H*3*S
#define PTS_W 576          // H*NPTS*3
#define XYW   2112         // QKV_W + PTS_W (merged gemm12 output width)
#define FEATS 1792         // H*CP + H*S + H*P*3 + H*P

// ---------------- scratch (device globals; no allocations allowed) ----------
__device__ __align__(16) __half g_xh[NRES * DMODEL];      // LN(local), fp16
__device__ __align__(16) __half g_xyh[NRES * XYW];        // [qkv | raw] fp16
__device__ __align__(16) __half g_kvh[NRES * NHEAD * 128];// per (n,h): k(64,LN) | v(64)
__device__ __align__(16) __half g_vgh[NRES * NHEAD * 24]; // fp16 v_g coords
__device__ __align__(16) float  g_pts[NRES * PTS_W];      // rotated points (fp32)
__device__ __align__(16) float  g_R[NRES * 9];
__device__ __align__(16) float  g_t[NRES * 3];
__device__ __align__(16) __half g_featsh[NRES * FEATS];   // fp16 feats
__device__ __align__(16) float  g_part[2 * NRES * DMODEL];// split-K partials
// fp16 weight copies
__device__ __align__(16) __half g_w12h[DMODEL * XYW];     // [W_qkv | W_pts]
__device__ __align__(16) __half g_woh[FEATS * DMODEL];

__device__ __forceinline__ void cp_async16(uint32_t saddr, const void* gptr, int srcsize) {
    asm volatile("cp.async.cg.shared.global [%0], [%1], 16, %2;\n"
                 :: "r"(saddr), "l"(gptr), "r"(srcsize));
}

// ---------------- fp16 conversion copies --------------------------------------
__global__ void tohalf_kernel(const float* __restrict__ src,
                              __half* __restrict__ dst, int n4)
{
    int i = blockIdx.x * blockDim.x + threadIdx.x;
    if (i < n4) {
        float4 v = ((const float4*)src)[i];
        __half2 h0 = __floats2half2_rn(v.x, v.y);
        __half2 h1 = __floats2half2_rn(v.z, v.w);
        uint2 u; u.x = *(uint32_t*)&h0; u.y = *(uint32_t*)&h1;
        ((uint2*)dst)[i] = u;
    }
}

__global__ void tohalf_strided(const float* __restrict__ src,
                               __half* __restrict__ dst,
                               int cols, int dstStride, int dstOff, int n4)
{
    int i = blockIdx.x * blockDim.x + threadIdx.x;
    if (i >= n4) return;
    int c4 = cols >> 2;
    int row = i / c4, c = i - row * c4;
    float4 v = ((const float4*)src)[i];
    __half2 h0 = __floats2half2_rn(v.x, v.y);
    __half2 h1 = __floats2half2_rn(v.z, v.w);
    uint2 u; u.x = *(uint32_t*)&h0; u.y = *(uint32_t*)&h1;
    *(uint2*)&dst[(size_t)row * dstStride + dstOff + (c << 2)] = u;
}

// ---------------- LayerNorm over local (768 per row), fp16 out ---------------
__global__ __launch_bounds__(192) void ln_local_kernel(
    const float* __restrict__ local, const float* __restrict__ sc,
    const float* __restrict__ of, int n0)
{
    int n = blockIdx.x + n0;
    int tid = threadIdx.x;
    const float4* row4 = (const float4*)(local + (size_t)n * DMODEL);
    float4 v = row4[tid];

    __shared__ float red[6];
    float s = v.x + v.y + v.z + v.w;
    #pragma unroll
    for (int o = 16; o > 0; o >>= 1) s += __shfl_xor_sync(0xffffffffu, s, o);
    if ((tid & 31) == 0) red[tid >> 5] = s;
    __syncthreads();
    float total = 0.f;
    #pragma unroll
    for (int i = 0; i < 6; i++) total += red[i];
    float mean = total * (1.0f / DMODEL);

    float d0 = v.x - mean, d1 = v.y - mean, d2 = v.z - mean, d3 = v.w - mean;
    float vs = d0 * d0 + d1 * d1 + d2 * d2 + d3 * d3;
    __syncthreads();
    #pragma unroll
    for (int o = 16; o > 0; o >>= 1) vs += __shfl_xor_sync(0xffffffffu, vs, o);
    if ((tid & 31) == 0) red[tid >> 5] = vs;
    __syncthreads();
    float vtot = 0.f;
    #pragma unroll
    for (int i = 0; i < 6; i++) vtot += red[i];
    float inv = rsqrtf(vtot * (1.0f / DMODEL) + 1e-5f);

    float4 s4 = ((const float4*)sc)[tid];
    float4 o4 = ((const float4*)of)[tid];
    __half2 h0 = __floats2half2_rn(d0 * inv * s4.x + o4.x, d1 * inv * s4.y + o4.y);
    __half2 h1 = __floats2half2_rn(d2 * inv * s4.z + o4.z, d3 * inv * s4.w + o4.w);
    uint2 u; u.x = *(uint32_t*)&h0; u.y = *(uint32_t*)&h1;
    ((uint2*)(g_xh + (size_t)n * DMODEL))[tid] = u;
}

// ---------------- FP16 GEMM: 128x128 CTA tile, 4 warps of 64x64 --------------
#define ASTRH 40
#define BSTRH 136
#define A_HWORDS (128 * ASTRH)
#define B_HWORDS (32 * BSTRH)
#define NSTAGE 3
#define GEMM_SMEM_BYTES (NSTAGE * (A_HWORDS + B_HWORDS) * 2)

__device__ __forceinline__ void ldsm_x4(uint32_t& r0, uint32_t& r1, uint32_t& r2,
                                        uint32_t& r3, uint32_t addr) {
    asm volatile("ldmatrix.sync.aligned.m8n8.x4.shared.b16 {%0,%1,%2,%3}, [%4];"
                 : "=r"(r0), "=r"(r1), "=r"(r2), "=r"(r3) : "r"(addr));
}
__device__ __forceinline__ void ldsm_x4t(uint32_t& r0, uint32_t& r1, uint32_t& r2,
                                         uint32_t& r3, uint32_t addr) {
    asm volatile("ldmatrix.sync.aligned.m8n8.x4.trans.shared.b16 {%0,%1,%2,%3}, [%4];"
                 : "=r"(r0), "=r"(r1), "=r"(r2), "=r"(r3) : "r"(addr));
}

template <bool HALF_OUT>
__global__ __launch_bounds__(128, 2) void hgemm128(
    const __half* __restrict__ A, int lda,
    const __half* __restrict__ B,
    void* __restrict__ Cv, size_t zstride, int Ncol, int K)
{
    extern __shared__ __half smem_h[];
    __half* As = smem_h;
    __half* Bs = smem_h + NSTAGE * A_HWORDS;

    A += (size_t)blockIdx.z * K;
    B += (size_t)blockIdx.z * K * Ncol;
    size_t zoff = (size_t)blockIdx.z * zstride;

    int bm = blockIdx.y * 128;
    int bn = blockIdx.x * 128;
    int tid = threadIdx.x;
    int wid = tid >> 5, lane = tid & 31;
    int wm = (wid >> 1) * 64;
    int wn = (wid & 1) * 64;
    int lr = lane >> 2;
    int lc = lane & 3;
    int grp = lane >> 3;
    int lm_r = (grp & 1) * 8 + (lane & 7);
    int lm_c = (grp >> 1) * 8;

    float acc[4][8][4];
    #pragma unroll
    for (int im = 0; im < 4; im++)
        #pragma unroll
        for (int in = 0; in < 8; in++)
            #pragma unroll
            for (int r = 0; r < 4; r++) acc[im][in][r] = 0.f;

    int a_r[4], a_c[4], b_r[4], b_c[4];
    #pragma unroll
    for (int j = 0; j < 4; j++) {
        int i = tid + j * 128;
        a_r[j] = i >> 2;  a_c[j] = (i & 3) << 3;
        b_r[j] = i >> 4;  b_c[j] = (i & 15) << 3;
    }
    uint32_t as_base = (uint32_t)__cvta_generic_to_shared(As);
    uint32_t bs_base = (uint32_t)__cvta_generic_to_shared(Bs);

    auto issue = [&](int kt, int buf) {
        #pragma unroll
        for (int j = 0; j < 4; j++) {
            uint32_t sa = as_base + (buf * A_HWORDS + a_r[j] * ASTRH + a_c[j]) * 2;
            cp_async16(sa, &A[(size_t)(bm + a_r[j]) * lda + kt + a_c[j]], 16);
        }
        #pragma unroll
        for (int j = 0; j < 4; j++) {
            int col = bn + b_c[j];
            int ok = (col < Ncol);
            const __half* gp = &B[(size_t)(kt + b_r[j]) * Ncol + (ok ? col : 0)];
            uint32_t sb = bs_base + (buf * B_HWORDS + b_r[j] * BSTRH + b_c[j]) * 2;
            cp_async16(sb, gp, ok ? 16 : 0);
        }
        asm volatile("cp.async.commit_group;\n" ::);
    };

    auto compute = [&](int buf) {
        #pragma unroll
        for (int ks = 0; ks < 2; ks++) {
            int kk = ks * 16;
            uint32_t a[4][4], b[8][2];
            #pragma unroll
            for (int im = 0; im < 4; im++) {
                uint32_t addr = as_base +
                    (buf * A_HWORDS + (wm + im * 16 + lm_r) * ASTRH + kk + lm_c) * 2;
                ldsm_x4(a[im][0], a[im][1], a[im][2], a[im][3], addr);
            }
            #pragma unroll
            for (int in16 = 0; in16 < 4; in16++) {
                uint32_t addr = bs_base +
                    (buf * B_HWORDS + (kk + lm_r) * BSTRH + wn + in16 * 16 + lm_c) * 2;
                uint32_t r0, r1, r2, r3;
                ldsm_x4t(r0, r1, r2, r3, addr);
                b[in16 * 2][0] = r0;  b[in16 * 2][1] = r1;
                b[in16 * 2 + 1][0] = r2;  b[in16 * 2 + 1][1] = r3;
            }
            #pragma unroll
            for (int im = 0; im < 4; im++)
                #pragma unroll
                for (int in = 0; in < 8; in++) {
                    asm volatile(
                        "mma.sync.aligned.m16n8k16.row.col.f32.f16.f16.f32 "
                        "{%0,%1,%2,%3}, {%4,%5,%6,%7}, {%8,%9}, {%0,%1,%2,%3};"
                        : "+f"(acc[im][in][0]), "+f"(acc[im][in][1]),
                          "+f"(acc[im][in][2]), "+f"(acc[im][in][3])
                        : "r"(a[im][0]), "r"(a[im][1]), "r"(a[im][2]), "r"(a[im][3]),
                          "r"(b[in][0]), "r"(b[in][1]));
                }
        }
    };

    int T = K >> 5;
    issue(0, 0);
    issue(32, 1);
    for (int t = 0; t < T; t++) {
        if (t + 1 < T) { asm volatile("cp.async.wait_group 1;\n" ::); }
        else           { asm volatile("cp.async.wait_group 0;\n" ::); }
        __syncthreads();
        if (t + 2 < T) issue((t + 2) << 5, (t + 2) % NSTAGE);
        compute(t % NSTAGE);
    }

    #pragma unroll
    for (int im = 0; im < 4; im++) {
        int row0 = bm + wm + im * 16 + lr;
        #pragma unroll
        for (int in = 0; in < 8; in++) {
            int col = bn + wn + in * 8 + 2 * lc;
            if (col < Ncol) {
                if (HALF_OUT) {
                    __half* C = (__half*)Cv + zoff;
                    *(__half2*)&C[(size_t)row0 * Ncol + col] =
                        __floats2half2_rn(acc[im][in][0], acc[im][in][1]);
                    *(__half2*)&C[(size_t)(row0 + 8) * Ncol + col] =
                        __floats2half2_rn(acc[im][in][2], acc[im][in][3]);
                } else {
                    float* C = (float*)Cv + zoff;
                    C[(size_t)row0 * Ncol + col]           = acc[im][in][0];
                    C[(size_t)row0 * Ncol + col + 1]       = acc[im][in][1];
                    C[(size_t)(row0 + 8) * Ncol + col]     = acc[im][in][2];
                    C[(size_t)(row0 + 8) * Ncol + col + 1] = acc[im][in][3];
                }
            }
        }
    }
}

// ---------------- split-K reduce + bias (row-range version) ------------------
__global__ void reduce_bias_kernel(const float* __restrict__ bias,
                                   float* __restrict__ out, int e0)
{
    int i = blockIdx.x * blockDim.x + threadIdx.x + e0;  // element/4 index
    float4 a = ((const float4*)g_part)[i];
    float4 b = ((const float4*)(g_part + (size_t)NRES * DMODEL))[i];
    float4 bi = ((const float4*)bias)[i % (DMODEL / 4)];
    float4 o;
    o.x = a.x + b.x + bi.x; o.y = a.y + b.y + bi.y;
    o.z = a.z + b.z + bi.z; o.w = a.w + b.w + bi.w;
    ((float4*)out)[i] = o;
}

// ---------------- frames + LN(q,k) + fp16 caches + point rotation (fused) ----
__global__ __launch_bounds__(256) void ln_qk_pts_kernel(
    const float* __restrict__ pos,
    const float* __restrict__ qs, const float* __restrict__ qb,
    const float* __restrict__ ks, const float* __restrict__ kb, int n0)
{
    int n = blockIdx.x + n0;
    int tid = threadIdx.x;
    int w = tid >> 5, l = tid & 31;   // w = head
    __shared__ float sR[9], sT[3];

    if (tid == 0) {
        const float* p = pos + (size_t)n * 42;
        float nx = p[0], ny = p[1], nz = p[2];
        float cax = p[3], cay = p[4], caz = p[5];
        float cx = p[6], cy = p[7], cz = p[8];
        float v1x = cx - cax, v1y = cy - cay, v1z = cz - caz;
        float v2x = nx - cax, v2y = ny - cay, v2z = nz - caz;
        float inv1 = rsqrtf(v1x * v1x + v1y * v1y + v1z * v1z + 1e-8f);
        float e1x = v1x * inv1, e1y = v1y * inv1, e1z = v1z * inv1;
        float d = v2x * e1x + v2y * e1y + v2z * e1z;
        float u2x = v2x - d * e1x, u2y = v2y - d * e1y, u2z = v2z - d * e1z;
        float inv2 = rsqrtf(u2x * u2x + u2y * u2y + u2z * u2z + 1e-8f);
        float e2x = u2x * inv2, e2y = u2y * inv2, e2z = u2z * inv2;
        float e3x = e1y * e2z - e1z * e2y;
        float e3y = e1z * e2x - e1x * e2z;
        float e3z = e1x * e2y - e1y * e2x;
        sR[0] = e1x; sR[1] = e2x; sR[2] = e3x;
        sR[3] = e1y; sR[4] = e2y; sR[5] = e3y;
        sR[6] = e1z; sR[7] = e2z; sR[8] = e3z;
        sT[0] = cax; sT[1] = cay; sT[2] = caz;
        float* R = g_R + (size_t)n * 9;
        #pragma unroll
        for (int i = 0; i < 9; i++) R[i] = sR[i];
        g_t[n * 3 + 0] = cax; g_t[n * 3 + 1] = cay; g_t[n * 3 + 2] = caz;
    }

    size_t base = (size_t)n * XYW + w * 192;
    __half* kv = g_kvh + ((size_t)n * NHEAD + w) * 128;
    #pragma unroll
    for (int which = 0; which < 2; which++) {
        __half* v = g_xyh + base + (which ? 64 : 0);
        const float* sc = which ? ks : qs;
        const float* of = which ? kb : qb;
        float a = __half2float(v[l]), b = __half2float(v[l + 32]);
        float s = a + b;
        #pragma unroll
        for (int o = 16; o > 0; o >>= 1) s += __shfl_xor_sync(0xffffffffu, s, o);
        float mean = s * (1.0f / 64.0f);
        float da = a - mean, db = b - mean;
        float var = da * da + db * db;
        #pragma unroll
        for (int o = 16; o > 0; o >>= 1) var += __shfl_xor_sync(0xffffffffu, var, o);
        float inv = rsqrtf(var * (1.0f / 64.0f) + 1e-5f);
        __half r0 = __float2half_rn(da * inv * sc[l]      + of[l]);
        __half r1 = __float2half_rn(db * inv * sc[l + 32] + of[l + 32]);
        v[l]      = r0;
        v[l + 32] = r1;
        if (which == 1) { kv[l] = r0; kv[l + 32] = r1; }
    }
    {
        const __half* vsrc = g_xyh + base + 128;
        kv[64 + l] = vsrc[l];
        kv[96 + l] = vsrc[l + 32];
    }
    __syncthreads();

    float t0 = sT[0], t1 = sT[1], t2 = sT[2];
    for (int r = tid; r < PTS_W; r += 256) {
        int i = r % 3;
        const __half* src = g_xyh + (size_t)n * XYW + QKV_W + (r - i);
        float acc = (i == 0 ? t0 : (i == 1 ? t1 : t2));
        acc += sR[i * 3 + 0] * __half2float(src[0]);
        acc += sR[i * 3 + 1] * __half2float(src[1]);
        acc += sR[i * 3 + 2] * __half2float(src[2]);
        g_pts[(size_t)n * PTS_W + r] = acc;
        int h = r / 72, rr = r - h * 72;
        if (rr >= 48)
            g_vgh[(size_t)n * (NHEAD * 24) + h * 24 + (rr - 48)] = __float2half_rn(acc);
    }
}

// ---------------- fused attention: async pair + gather overlap ---------------
#define PSTR 132
__global__ __launch_bounds__(256) void attn_kernel(
    const float* __restrict__ pair, const int* __restrict__ nbr,
    const float* __restrict__ Wb, const float* __restrict__ gamma, int n0)
{
    __shared__ __align__(16) float sh_pair[32][PSTR];
    __shared__ __align__(16) float sh_q[8][64];
    __shared__ __align__(16) float sh_qg[8][24];
    __shared__ float sh_wb[128][8];
    __shared__ float sh_bias[32][8];
    __shared__ float sh_attn[32][8];
    __shared__ int   sh_nb[32];
    __shared__ float sh_R[9], sh_t[3], sh_df[8];

    int n = blockIdx.x + n0, tid = threadIdx.x;
    const float4* prow4 = (const float4*)(pair + (size_t)n * (KNBR * CPAIR));

    // 1) issue async pair tile fetch (DRAM) — overlapped with gather phase below
    uint32_t sp_base = (uint32_t)__cvta_generic_to_shared(&sh_pair[0][0]);
    #pragma unroll
    for (int j = 0; j < 4; j++) {
        int i = tid + j * 256;
        int r = i >> 5, c = (i & 31) << 2;
        cp_async16(sp_base + (r * PSTR + c) * 4, &prow4[i], 16);
    }
    asm volatile("cp.async.commit_group;\n" ::);

    // 2) scalar loads for gather phase
    for (int i = tid; i < CPAIR * NHEAD; i += 256) ((float*)sh_wb)[i] = Wb[i];
    if (tid < 32) sh_nb[tid] = nbr[n * KNBR + tid];
    for (int i = tid; i < NHEAD * SDIM; i += 256) {
        int h = i >> 6, s = i & 63;
        sh_q[h][s] = __half2float(g_xyh[(size_t)n * XYW + h * 192 + s]);
    }
    if (tid < NHEAD * NPTS)
        ((float*)sh_qg)[tid] = g_pts[(size_t)n * PTS_W + (tid / 24) * 72 + (tid % 24)];
    if (tid < 9) sh_R[tid] = g_R[(size_t)n * 9 + tid];
    if (tid < 3) sh_t[tid] = g_t[n * 3 + tid];
    if (tid < 8) sh_df[tid] = log1pf(__expf(gamma[tid])) * (0.16666667f * 0.5f);
    __syncthreads();

    // 3) gather-dependent logit partial (kept in register; same mapping as softmax)
    const int lh = tid >> 5, lk = tid & 31;
    float part_lh;
    {
        int nb = sh_nb[lk];
        const uint4* k8 = (const uint4*)(g_kvh + ((size_t)nb * NHEAD + lh) * 128);
        const float4* q4 = (const float4*)sh_q[lh];
        float dot = 0.f;
        #pragma unroll
        for (int s = 0; s < 8; s++) {
            uint4 kv = __ldg(&k8[s]);
            float4 qa = q4[s * 2], qb = q4[s * 2 + 1];
            float2 f0 = __half22float2(*(__half2*)&kv.x);
            float2 f1 = __half22float2(*(__half2*)&kv.y);
            float2 f2 = __half22float2(*(__half2*)&kv.z);
            float2 f3 = __half22float2(*(__half2*)&kv.w);
            dot += qa.x * f0.x + qa.y * f0.y + qa.z * f1.x + qa.w * f1.y;
            dot += qb.x * f2.x + qb.y * f2.y + qb.z * f3.x + qb.w * f3.y;
        }
        const float4* kg4 = (const float4*)(g_pts + (size_t)nb * PTS_W + lh * 72 + 24);
        const float4* qg4 = (const float4*)sh_qg[lh];
        float dist = 0.f;
        #pragma unroll
        for (int r = 0; r < 6; r++) {
            float4 kgv = __ldg(&kg4[r]);
            float4 qgv = qg4[r];
            float d0 = qgv.x - kgv.x, d1 = qgv.y - kgv.y;
            float d2 = qgv.z - kgv.z, d3 = qgv.w - kgv.w;
            dist += d0 * d0 + d1 * d1 + d2 * d2 + d3 * d3;
        }
        part_lh = 0.125f * dot - sh_df[lh] * dist;
    }

    // 4) pair tile now needed: wait + sync
    asm volatile("cp.async.wait_group 0;\n" ::);
    __syncthreads();

    // 5) bias[k][h] = pair[n,k,:] . W_bias[:,h]
    {
        int k = tid >> 3, h = tid & 7;
        float acc = 0.f;
        #pragma unroll 8
        for (int c = 0; c < CPAIR; c++) acc += sh_pair[k][c] * sh_wb[c][h];
        sh_bias[k][h] = acc;
    }
    __syncthreads();

    // 6) combine + softmax (warp lh, lane lk)
    {
        float logit = 0.57735027f * (part_lh + sh_bias[lk][lh]);
        float m = logit;
        #pragma unroll
        for (int o = 16; o > 0; o >>= 1) m = fmaxf(m, __shfl_xor_sync(0xffffffffu, m, o));
        float e = __expf(logit - m);
        float ssum = e;
        #pragma unroll
        for (int o = 16; o > 0; o >>= 1) ssum += __shfl_xor_sync(0xffffffffu, ssum, o);
        sh_attn[lk][lh] = e / ssum;
    }
    __syncthreads();

    __half* frow = g_featsh + (size_t)n * FEATS;

    {
        int h = tid >> 5, c4 = tid & 31;
        float4 acc = make_float4(0.f, 0.f, 0.f, 0.f);
        #pragma unroll
        for (int k = 0; k < KNBR; k++) {
            float a = sh_attn[k][h];
            float4 pv = *(const float4*)&sh_pair[k][c4 << 2];
            acc.x += a * pv.x; acc.y += a * pv.y;
            acc.z += a * pv.z; acc.w += a * pv.w;
        }
        __half2 h0 = __floats2half2_rn(acc.x, acc.y);
        __half2 h1 = __floats2half2_rn(acc.z, acc.w);
        uint2 u; u.x = *(uint32_t*)&h0; u.y = *(uint32_t*)&h1;
        ((uint2*)frow)[tid] = u;
    }

    if (tid < 64) {
        int h = tid >> 3, s8 = tid & 7;
        float acc[8];
        #pragma unroll
        for (int j = 0; j < 8; j++) acc[j] = 0.f;
        #pragma unroll
        for (int k = 0; k < KNBR; k++) {
            float a = sh_attn[k][h];
            uint4 vv = __ldg((const uint4*)(g_kvh + ((size_t)sh_nb[k] * NHEAD + h) * 128
                                            + 64 + s8 * 8));
            float2 f0 = __half22float2(*(__half2*)&vv.x);
            float2 f1 = __half22float2(*(__half2*)&vv.y);
            float2 f2 = __half22float2(*(__half2*)&vv.z);
            float2 f3 = __half22float2(*(__half2*)&vv.w);
            acc[0] += a * f0.x; acc[1] += a * f0.y;
            acc[2] += a * f1.x; acc[3] += a * f1.y;
            acc[4] += a * f2.x; acc[5] += a * f2.y;
            acc[6] += a * f3.x; acc[7] += a * f3.y;
        }
        __half2 h0 = __floats2half2_rn(acc[0], acc[1]);
        __half2 h1 = __floats2half2_rn(acc[2], acc[3]);
        __half2 h2 = __floats2half2_rn(acc[4], acc[5]);
        __half2 h3 = __floats2half2_rn(acc[6], acc[7]);
        uint4 u; u.x = *(uint32_t*)&h0; u.y = *(uint32_t*)&h1;
        u.z = *(uint32_t*)&h2; u.w = *(uint32_t*)&h3;
        *(uint4*)(frow + 1024 + h * 64 + s8 * 8) = u;
    } else if (tid < 128) {
        int t2 = tid - 64;
        int h = t2 >> 3, p = t2 & 7;
        float o0 = 0.f, o1 = 0.f, o2 = 0.f;
        #pragma unroll
        for (int k = 0; k < KNBR; k++) {
            float a = sh_attn[k][h];
            const __half* vg = g_vgh + (size_t)sh_nb[k] * (NHEAD * 24) + h * 24 + p * 3;
            o0 += a * __half2float(__ldg(&vg[0]));
            o1 += a * __half2float(__ldg(&vg[1]));
            o2 += a * __half2float(__ldg(&vg[2]));
        }
        o0 -= sh_t[0]; o1 -= sh_t[1]; o2 -= sh_t[2];
        float nrm = 0.f;
        #pragma unroll
        for (int i2 = 0; i2 < 3; i2++) {
            float v = sh_R[0 * 3 + i2] * o0 + sh_R[1 * 3 + i2] * o1 + sh_R[2 * 3 + i2] * o2;
            frow[1536 + h * 24 + p * 3 + i2] = __float2half_rn(v);
            nrm += v * v;
        }
        frow[1728 + h * 8 + p] = __float2half_rn(sqrtf(nrm + 1e-8f));
    }
}

// ---------------- launch -----------------------------------------------------
extern "C" void kernel_launch(void* const* d_in, const int* in_sizes, int n_in,
                              void* d_out, int out_size)
{
    const float* local      = (const float*)d_in[0];
    const float* pos        = (const float*)d_in[1];
    const float* pair       = (const float*)d_in[2];
    const int*   neighbours = (const int*)d_in[4];
    const float* ln_s       = (const float*)d_in[9];
    const float* ln_b       = (const float*)d_in[10];
    const float* W_qkv      = (const float*)d_in[11];
    const float* ln_q_s     = (const float*)d_in[12];
    const float* ln_q_b     = (const float*)d_in[13];
    const float* ln_k_s     = (const float*)d_in[14];
    const float* ln_k_b     = (const float*)d_in[15];
    const float* W_pts      = (const float*)d_in[16];
    const float* W_bias     = (const float*)d_in[17];
    const float* gamma      = (const float*)d_in[18];
    const float* W_out      = (const float*)d_in[19];
    const float* b_out      = (const float*)d_in[20];
    float* out = (float*)d_out;

    __half *xh, *xyh, *featsh, *w12h, *woh;
    float *part;
    cudaGetSymbolAddress((void**)&xh, g_xh);
    cudaGetSymbolAddress((void**)&xyh, g_xyh);
    cudaGetSymbolAddress((void**)&featsh, g_featsh);
    cudaGetSymbolAddress((void**)&w12h, g_w12h);
    cudaGetSymbolAddress((void**)&woh, g_woh);
    cudaGetSymbolAddress((void**)&part, g_part);

    static cudaStream_t s2 = nullptr;
    static cudaEvent_t evStart, evW, evLL1, evG0, evL0, evA0, evG2;
    static bool init = false;
    if (!init) {
        cudaFuncSetAttribute(hgemm128<true>, cudaFuncAttributeMaxDynamicSharedMemorySize,
                             GEMM_SMEM_BYTES);
        cudaFuncSetAttribute(hgemm128<false>, cudaFuncAttributeMaxDynamicSharedMemorySize,
                             GEMM_SMEM_BYTES);
        cudaStreamCreateWithFlags(&s2, cudaStreamNonBlocking);
        cudaEventCreateWithFlags(&evStart, cudaEventDisableTiming);
        cudaEventCreateWithFlags(&evW, cudaEventDisableTiming);
        cudaEventCreateWithFlags(&evLL1, cudaEventDisableTiming);
        cudaEventCreateWithFlags(&evG0, cudaEventDisableTiming);
        cudaEventCreateWithFlags(&evL0, cudaEventDisableTiming);
        cudaEventCreateWithFlags(&evA0, cudaEventDisableTiming);
        cudaEventCreateWithFlags(&evG2, cudaEventDisableTiming);
        init = true;
    }

    // fork: s2 handles weight conversions + ln_local half1
    cudaEventRecord(evStart, 0);
    cudaStreamWaitEvent(s2, evStart, 0);

    tohalf_strided<<<(DMODEL * QKV_W / 4 + 255) / 256, 256, 0, s2>>>(
        W_qkv, w12h, QKV_W, XYW, 0, DMODEL * QKV_W / 4);
    tohalf_strided<<<(DMODEL * PTS_W / 4 + 255) / 256, 256, 0, s2>>>(
        W_pts, w12h, PTS_W, XYW, QKV_W, DMODEL * PTS_W / 4);
    tohalf_kernel<<<(FEATS * DMODEL / 4 + 255) / 256, 256, 0, s2>>>(
        W_out, woh, FEATS * DMODEL / 4);
    cudaEventRecord(evW, s2);
    ln_local_kernel<<<HALF_N, 192, 0, s2>>>(local, ln_s, ln_b, HALF_N);
    cudaEventRecord(evLL1, s2);

    // main: ln_local half0, then gemm1 half0 (needs weights + x half0 only)
    ln_local_kernel<<<HALF_N, 192>>>(local, ln_s, ln_b, 0);
    cudaStreamWaitEvent(0, evW, 0);
    hgemm128<true><<<dim3((XYW + 127) / 128, HALF_N / 128, 1), 128, GEMM_SMEM_BYTES>>>(
        xh, DMODEL, w12h, xyh, 0, XYW, DMODEL);
    cudaEventRecord(evG0, 0);
    cudaStreamWaitEvent(0, evLL1, 0);
    hgemm128<true><<<dim3((XYW + 127) / 128, HALF_N / 128, 1), 128, GEMM_SMEM_BYTES>>>(
        xh + (size_t)HALF_N * DMODEL, DMODEL, w12h,
        xyh + (size_t)HALF_N * XYW, 0, XYW, DMODEL);

    // lnqk half0 on s2 (after gemm1 half0), half1 on main (after gemm1 half1)
    cudaStreamWaitEvent(s2, evG0, 0);
    ln_qk_pts_kernel<<<HALF_N, 256, 0, s2>>>(pos, ln_q_s, ln_q_b, ln_k_s, ln_k_b, 0);
    cudaEventRecord(evL0, s2);
    ln_qk_pts_kernel<<<HALF_N, 256>>>(pos, ln_q_s, ln_q_b, ln_k_s, ln_k_b, HALF_N);
    cudaStreamWaitEvent(0, evL0, 0);

    // attn halves on main; gemm2 half0 (+ its reduce) on s2 overlaps attn half1
    attn_kernel<<<HALF_N, 256>>>(pair, neighbours, W_bias, gamma, 0);
    cudaEventRecord(evA0, 0);
    attn_kernel<<<HALF_N, 256>>>(pair, neighbours, W_bias, gamma, HALF_N);

    cudaStreamWaitEvent(s2, evA0, 0);
    hgemm128<false><<<dim3(DMODEL / 128, HALF_N / 128, 2), 128, GEMM_SMEM_BYTES, s2>>>(
        featsh, FEATS, woh, part, (size_t)NRES * DMODEL, DMODEL, FEATS / 2);
    reduce_bias_kernel<<<HALF_N * DMODEL / 4 / 256, 256, 0, s2>>>(b_out, out, 0);
    cudaEventRecord(evG2, s2);

    hgemm128<false><<<dim3(DMODEL / 128, HALF_N / 128, 2), 128, GEMM_SMEM_BYTES>>>(
        featsh + (size_t)HALF_N * FEATS, FEATS, woh,
        part + (size_t)HALF_N * DMODEL, (size_t)NRES * DMODEL, DMODEL, FEATS / 2);
    reduce_bias_kernel<<<HALF_N * DMODEL / 4 / 256, 256>>>(b_out, out,
                                                           HALF_N * DMODEL / 4);
    cudaStreamWaitEvent(0, evG2, 0);
}

// round 16
// speedup vs baseline: 1.0088x; 1.0088x over previous
#include <cuda_runtime.h>
#include <cuda_fp16.h>
#include <cstdint>

// Problem constants
#define NRES 8192
#define HALF_N 4096
#define KNBR 32
#define DMODEL 768
#define CPAIR 128
#define NHEAD 8
#define SDIM 64
#define PPTS 8
#define NPTS 24            // 3*P
#define QKV_W 1536         // H*3*S
#define PTS_W 576          // H*NPTS*3
#define XYW   2112         // QKV_W + PTS_W (merged gemm12 output width)
#define FEATS 1792         // H*CP + H*S + H*P*3 + H*P

// ---------------- scratch (device globals; no allocations allowed) ----------
__device__ __align__(16) __half g_xh[NRES * DMODEL];      // LN(local), fp16
__device__ __align__(16) __half g_xyh[NRES * XYW];        // [qkv | raw] fp16
__device__ __align__(16) __half g_kvh[NRES * NHEAD * 128];// per (n,h): k(64,LN) | v(64)
__device__ __align__(16) __half g_vgh[NRES * NHEAD * 24]; // fp16 v_g coords
__device__ __align__(16) float  g_pts[NRES * PTS_W];      // rotated points (fp32)
__device__ __align__(16) float  g_R[NRES * 9];
__device__ __align__(16) float  g_t[NRES * 3];
__device__ __align__(16) __half g_featsh[NRES * FEATS];   // fp16 feats
__device__ __align__(16) float  g_part[2 * NRES * DMODEL];// split-K partials
// fp16 weight copies
__device__ __align__(16) __half g_w12h[DMODEL * XYW];     // [W_qkv | W_pts]
__device__ __align__(16) __half g_woh[FEATS * DMODEL];

// ---------------- fp16 conversion copies --------------------------------------
__global__ void tohalf_kernel(const float* __restrict__ src,
                              __half* __restrict__ dst, int n4)
{
    int i = blockIdx.x * blockDim.x + threadIdx.x;
    if (i < n4) {
        float4 v = ((const float4*)src)[i];
        __half2 h0 = __floats2half2_rn(v.x, v.y);
        __half2 h1 = __floats2half2_rn(v.z, v.w);
        uint2 u; u.x = *(uint32_t*)&h0; u.y = *(uint32_t*)&h1;
        ((uint2*)dst)[i] = u;
    }
}

__global__ void tohalf_strided(const float* __restrict__ src,
                               __half* __restrict__ dst,
                               int cols, int dstStride, int dstOff, int n4)
{
    int i = blockIdx.x * blockDim.x + threadIdx.x;
    if (i >= n4) return;
    int c4 = cols >> 2;
    int row = i / c4, c = i - row * c4;
    float4 v = ((const float4*)src)[i];
    __half2 h0 = __floats2half2_rn(v.x, v.y);
    __half2 h1 = __floats2half2_rn(v.z, v.w);
    uint2 u; u.x = *(uint32_t*)&h0; u.y = *(uint32_t*)&h1;
    *(uint2*)&dst[(size_t)row * dstStride + dstOff + (c << 2)] = u;
}

// ---------------- LayerNorm over local (768 per row), fp16 out ---------------
__global__ __launch_bounds__(192) void ln_local_kernel(
    const float* __restrict__ local, const float* __restrict__ sc,
    const float* __restrict__ of)
{
    int n = blockIdx.x;
    int tid = threadIdx.x;
    const float4* row4 = (const float4*)(local + (size_t)n * DMODEL);
    float4 v = row4[tid];

    __shared__ float red[6];
    float s = v.x + v.y + v.z + v.w;
    #pragma unroll
    for (int o = 16; o > 0; o >>= 1) s += __shfl_xor_sync(0xffffffffu, s, o);
    if ((tid & 31) == 0) red[tid >> 5] = s;
    __syncthreads();
    float total = 0.f;
    #pragma unroll
    for (int i = 0; i < 6; i++) total += red[i];
    float mean = total * (1.0f / DMODEL);

    float d0 = v.x - mean, d1 = v.y - mean, d2 = v.z - mean, d3 = v.w - mean;
    float vs = d0 * d0 + d1 * d1 + d2 * d2 + d3 * d3;
    __syncthreads();
    #pragma unroll
    for (int o = 16; o > 0; o >>= 1) vs += __shfl_xor_sync(0xffffffffu, vs, o);
    if ((tid & 31) == 0) red[tid >> 5] = vs;
    __syncthreads();
    float vtot = 0.f;
    #pragma unroll
    for (int i = 0; i < 6; i++) vtot += red[i];
    float inv = rsqrtf(vtot * (1.0f / DMODEL) + 1e-5f);

    float4 s4 = ((const float4*)sc)[tid];
    float4 o4 = ((const float4*)of)[tid];
    __half2 h0 = __floats2half2_rn(d0 * inv * s4.x + o4.x, d1 * inv * s4.y + o4.y);
    __half2 h1 = __floats2half2_rn(d2 * inv * s4.z + o4.z, d3 * inv * s4.w + o4.w);
    uint2 u; u.x = *(uint32_t*)&h0; u.y = *(uint32_t*)&h1;
    ((uint2*)(g_xh + (size_t)n * DMODEL))[tid] = u;
}

// ---------------- FP16 GEMM: 128x128 CTA tile, 4 warps of 64x64 --------------
#define ASTRH 40
#define BSTRH 136
#define A_HWORDS (128 * ASTRH)
#define B_HWORDS (32 * BSTRH)
#define NSTAGE 3
#define GEMM_SMEM_BYTES (NSTAGE * (A_HWORDS + B_HWORDS) * 2)

__device__ __forceinline__ void cp_async16(uint32_t saddr, const void* gptr, int srcsize) {
    asm volatile("cp.async.cg.shared.global [%0], [%1], 16, %2;\n"
                 :: "r"(saddr), "l"(gptr), "r"(srcsize));
}
__device__ __forceinline__ void ldsm_x4(uint32_t& r0, uint32_t& r1, uint32_t& r2,
                                        uint32_t& r3, uint32_t addr) {
    asm volatile("ldmatrix.sync.aligned.m8n8.x4.shared.b16 {%0,%1,%2,%3}, [%4];"
                 : "=r"(r0), "=r"(r1), "=r"(r2), "=r"(r3) : "r"(addr));
}
__device__ __forceinline__ void ldsm_x4t(uint32_t& r0, uint32_t& r1, uint32_t& r2,
                                         uint32_t& r3, uint32_t addr) {
    asm volatile("ldmatrix.sync.aligned.m8n8.x4.trans.shared.b16 {%0,%1,%2,%3}, [%4];"
                 : "=r"(r0), "=r"(r1), "=r"(r2), "=r"(r3) : "r"(addr));
}

template <bool HALF_OUT>
__global__ __launch_bounds__(128, 2) void hgemm128(
    const __half* __restrict__ A, int lda,
    const __half* __restrict__ B,
    void* __restrict__ Cv, size_t zstride, int Ncol, int K)
{
    extern __shared__ __half smem_h[];
    __half* As = smem_h;
    __half* Bs = smem_h + NSTAGE * A_HWORDS;

    A += (size_t)blockIdx.z * K;
    B += (size_t)blockIdx.z * K * Ncol;
    size_t zoff = (size_t)blockIdx.z * zstride;

    int bm = blockIdx.y * 128;
    int bn = blockIdx.x * 128;
    int tid = threadIdx.x;
    int wid = tid >> 5, lane = tid & 31;
    int wm = (wid >> 1) * 64;
    int wn = (wid & 1) * 64;
    int lr = lane >> 2;
    int lc = lane & 3;
    int grp = lane >> 3;
    int lm_r = (grp & 1) * 8 + (lane & 7);
    int lm_c = (grp >> 1) * 8;

    float acc[4][8][4];
    #pragma unroll
    for (int im = 0; im < 4; im++)
        #pragma unroll
        for (int in = 0; in < 8; in++)
            #pragma unroll
            for (int r = 0; r < 4; r++) acc[im][in][r] = 0.f;

    int a_r[4], a_c[4], b_r[4], b_c[4];
    #pragma unroll
    for (int j = 0; j < 4; j++) {
        int i = tid + j * 128;
        a_r[j] = i >> 2;  a_c[j] = (i & 3) << 3;
        b_r[j] = i >> 4;  b_c[j] = (i & 15) << 3;
    }
    uint32_t as_base = (uint32_t)__cvta_generic_to_shared(As);
    uint32_t bs_base = (uint32_t)__cvta_generic_to_shared(Bs);

    auto issue = [&](int kt, int buf) {
        #pragma unroll
        for (int j = 0; j < 4; j++) {
            uint32_t sa = as_base + (buf * A_HWORDS + a_r[j] * ASTRH + a_c[j]) * 2;
            cp_async16(sa, &A[(size_t)(bm + a_r[j]) * lda + kt + a_c[j]], 16);
        }
        #pragma unroll
        for (int j = 0; j < 4; j++) {
            int col = bn + b_c[j];
            int ok = (col < Ncol);
            const __half* gp = &B[(size_t)(kt + b_r[j]) * Ncol + (ok ? col : 0)];
            uint32_t sb = bs_base + (buf * B_HWORDS + b_r[j] * BSTRH + b_c[j]) * 2;
            cp_async16(sb, gp, ok ? 16 : 0);
        }
        asm volatile("cp.async.commit_group;\n" ::);
    };

    auto compute = [&](int buf) {
        #pragma unroll
        for (int ks = 0; ks < 2; ks++) {
            int kk = ks * 16;
            uint32_t a[4][4], b[8][2];
            #pragma unroll
            for (int im = 0; im < 4; im++) {
                uint32_t addr = as_base +
                    (buf * A_HWORDS + (wm + im * 16 + lm_r) * ASTRH + kk + lm_c) * 2;
                ldsm_x4(a[im][0], a[im][1], a[im][2], a[im][3], addr);
            }
            #pragma unroll
            for (int in16 = 0; in16 < 4; in16++) {
                uint32_t addr = bs_base +
                    (buf * B_HWORDS + (kk + lm_r) * BSTRH + wn + in16 * 16 + lm_c) * 2;
                uint32_t r0, r1, r2, r3;
                ldsm_x4t(r0, r1, r2, r3, addr);
                b[in16 * 2][0] = r0;  b[in16 * 2][1] = r1;
                b[in16 * 2 + 1][0] = r2;  b[in16 * 2 + 1][1] = r3;
            }
            #pragma unroll
            for (int im = 0; im < 4; im++)
                #pragma unroll
                for (int in = 0; in < 8; in++) {
                    asm volatile(
                        "mma.sync.aligned.m16n8k16.row.col.f32.f16.f16.f32 "
                        "{%0,%1,%2,%3}, {%4,%5,%6,%7}, {%8,%9}, {%0,%1,%2,%3};"
                        : "+f"(acc[im][in][0]), "+f"(acc[im][in][1]),
                          "+f"(acc[im][in][2]), "+f"(acc[im][in][3])
                        : "r"(a[im][0]), "r"(a[im][1]), "r"(a[im][2]), "r"(a[im][3]),
                          "r"(b[in][0]), "r"(b[in][1]));
                }
        }
    };

    int T = K >> 5;
    issue(0, 0);
    issue(32, 1);
    for (int t = 0; t < T; t++) {
        if (t + 1 < T) { asm volatile("cp.async.wait_group 1;\n" ::); }
        else           { asm volatile("cp.async.wait_group 0;\n" ::); }
        __syncthreads();
        if (t + 2 < T) issue((t + 2) << 5, (t + 2) % NSTAGE);
        compute(t % NSTAGE);
    }

    #pragma unroll
    for (int im = 0; im < 4; im++) {
        int row0 = bm + wm + im * 16 + lr;
        #pragma unroll
        for (int in = 0; in < 8; in++) {
            int col = bn + wn + in * 8 + 2 * lc;
            if (col < Ncol) {
                if (HALF_OUT) {
                    __half* C = (__half*)Cv + zoff;
                    *(__half2*)&C[(size_t)row0 * Ncol + col] =
                        __floats2half2_rn(acc[im][in][0], acc[im][in][1]);
                    *(__half2*)&C[(size_t)(row0 + 8) * Ncol + col] =
                        __floats2half2_rn(acc[im][in][2], acc[im][in][3]);
                } else {
                    float* C = (float*)Cv + zoff;
                    C[(size_t)row0 * Ncol + col]           = acc[im][in][0];
                    C[(size_t)row0 * Ncol + col + 1]       = acc[im][in][1];
                    C[(size_t)(row0 + 8) * Ncol + col]     = acc[im][in][2];
                    C[(size_t)(row0 + 8) * Ncol + col + 1] = acc[im][in][3];
                }
            }
        }
    }
}

// ---------------- split-K reduce + bias (row-range version) ------------------
__global__ void reduce_bias_kernel(const float* __restrict__ bias,
                                   float* __restrict__ out, int e0)
{
    int i = blockIdx.x * blockDim.x + threadIdx.x + e0;  // element/4 index
    float4 a = ((const float4*)g_part)[i];
    float4 b = ((const float4*)(g_part + (size_t)NRES * DMODEL))[i];
    float4 bi = ((const float4*)bias)[i % (DMODEL / 4)];
    float4 o;
    o.x = a.x + b.x + bi.x; o.y = a.y + b.y + bi.y;
    o.z = a.z + b.z + bi.z; o.w = a.w + b.w + bi.w;
    ((float4*)out)[i] = o;
}

// ---------------- frames + LN(q,k) + fp16 caches + point rotation (fused) ----
__global__ __launch_bounds__(256) void ln_qk_pts_kernel(
    const float* __restrict__ pos,
    const float* __restrict__ qs, const float* __restrict__ qb,
    const float* __restrict__ ks, const float* __restrict__ kb, int n0)
{
    int n = blockIdx.x + n0;
    int tid = threadIdx.x;
    int w = tid >> 5, l = tid & 31;   // w = head
    __shared__ float sR[9], sT[3];

    if (tid == 0) {
        const float* p = pos + (size_t)n * 42;
        float nx = p[0], ny = p[1], nz = p[2];
        float cax = p[3], cay = p[4], caz = p[5];
        float cx = p[6], cy = p[7], cz = p[8];
        float v1x = cx - cax, v1y = cy - cay, v1z = cz - caz;
        float v2x = nx - cax, v2y = ny - cay, v2z = nz - caz;
        float inv1 = rsqrtf(v1x * v1x + v1y * v1y + v1z * v1z + 1e-8f);
        float e1x = v1x * inv1, e1y = v1y * inv1, e1z = v1z * inv1;
        float d = v2x * e1x + v2y * e1y + v2z * e1z;
        float u2x = v2x - d * e1x, u2y = v2y - d * e1y, u2z = v2z - d * e1z;
        float inv2 = rsqrtf(u2x * u2x + u2y * u2y + u2z * u2z + 1e-8f);
        float e2x = u2x * inv2, e2y = u2y * inv2, e2z = u2z * inv2;
        float e3x = e1y * e2z - e1z * e2y;
        float e3y = e1z * e2x - e1x * e2z;
        float e3z = e1x * e2y - e1y * e2x;
        sR[0] = e1x; sR[1] = e2x; sR[2] = e3x;
        sR[3] = e1y; sR[4] = e2y; sR[5] = e3y;
        sR[6] = e1z; sR[7] = e2z; sR[8] = e3z;
        sT[0] = cax; sT[1] = cay; sT[2] = caz;
        float* R = g_R + (size_t)n * 9;
        #pragma unroll
        for (int i = 0; i < 9; i++) R[i] = sR[i];
        g_t[n * 3 + 0] = cax; g_t[n * 3 + 1] = cay; g_t[n * 3 + 2] = caz;
    }

    size_t base = (size_t)n * XYW + w * 192;
    __half* kv = g_kvh + ((size_t)n * NHEAD + w) * 128;
    #pragma unroll
    for (int which = 0; which < 2; which++) {
        __half* v = g_xyh + base + (which ? 64 : 0);
        const float* sc = which ? ks : qs;
        const float* of = which ? kb : qb;
        float a = __half2float(v[l]), b = __half2float(v[l + 32]);
        float s = a + b;
        #pragma unroll
        for (int o = 16; o > 0; o >>= 1) s += __shfl_xor_sync(0xffffffffu, s, o);
        float mean = s * (1.0f / 64.0f);
        float da = a - mean, db = b - mean;
        float var = da * da + db * db;
        #pragma unroll
        for (int o = 16; o > 0; o >>= 1) var += __shfl_xor_sync(0xffffffffu, var, o);
        float inv = rsqrtf(var * (1.0f / 64.0f) + 1e-5f);
        __half r0 = __float2half_rn(da * inv * sc[l]      + of[l]);
        __half r1 = __float2half_rn(db * inv * sc[l + 32] + of[l + 32]);
        v[l]      = r0;
        v[l + 32] = r1;
        if (which == 1) { kv[l] = r0; kv[l + 32] = r1; }
    }
    {
        const __half* vsrc = g_xyh + base + 128;
        kv[64 + l] = vsrc[l];
        kv[96 + l] = vsrc[l + 32];
    }
    __syncthreads();

    float t0 = sT[0], t1 = sT[1], t2 = sT[2];
    for (int r = tid; r < PTS_W; r += 256) {
        int i = r % 3;
        const __half* src = g_xyh + (size_t)n * XYW + QKV_W + (r - i);
        float acc = (i == 0 ? t0 : (i == 1 ? t1 : t2));
        acc += sR[i * 3 + 0] * __half2float(src[0]);
        acc += sR[i * 3 + 1] * __half2float(src[1]);
        acc += sR[i * 3 + 2] * __half2float(src[2]);
        g_pts[(size_t)n * PTS_W + r] = acc;
        int h = r / 72, rr = r - h * 72;
        if (rr >= 48)
            g_vgh[(size_t)n * (NHEAD * 24) + h * 24 + (rr - 48)] = __float2half_rn(acc);
    }
}

// ---------------- fused attention: bias + logits + softmax + outputs ---------
#define PSTR 132
__global__ __launch_bounds__(256) void attn_kernel(
    const float* __restrict__ pair, const int* __restrict__ nbr,
    const float* __restrict__ Wb, const float* __restrict__ gamma, int n0)
{
    __shared__ __align__(16) float sh_pair[32][PSTR];
    __shared__ __align__(16) float sh_q[8][64];
    __shared__ __align__(16) float sh_qg[8][24];
    __shared__ float sh_wb[128][8];
    __shared__ float sh_bias[32][8];
    __shared__ float sh_attn[32][8];
    __shared__ int   sh_nb[32];
    __shared__ float sh_R[9], sh_t[3], sh_df[8];

    int n = blockIdx.x + n0, tid = threadIdx.x;
    const float4* prow4 = (const float4*)(pair + (size_t)n * (KNBR * CPAIR));

    #pragma unroll
    for (int j = 0; j < 4; j++) {
        int i = tid + j * 256;
        int r = i >> 5, c = (i & 31) << 2;
        *(float4*)&sh_pair[r][c] = prow4[i];
    }
    for (int i = tid; i < CPAIR * NHEAD; i += 256) ((float*)sh_wb)[i] = Wb[i];
    if (tid < 32) sh_nb[tid] = nbr[n * KNBR + tid];
    for (int i = tid; i < NHEAD * SDIM; i += 256) {
        int h = i >> 6, s = i & 63;
        sh_q[h][s] = __half2float(g_xyh[(size_t)n * XYW + h * 192 + s]);
    }
    if (tid < NHEAD * NPTS)
        ((float*)sh_qg)[tid] = g_pts[(size_t)n * PTS_W + (tid / 24) * 72 + (tid % 24)];
    if (tid < 9) sh_R[tid] = g_R[(size_t)n * 9 + tid];
    if (tid < 3) sh_t[tid] = g_t[n * 3 + tid];
    if (tid < 8) sh_df[tid] = log1pf(__expf(gamma[tid])) * (0.16666667f * 0.5f);
    __syncthreads();

    {
        int k = tid >> 3, h = tid & 7;
        float acc = 0.f;
        #pragma unroll 8
        for (int c = 0; c < CPAIR; c++) acc += sh_pair[k][c] * sh_wb[c][h];
        sh_bias[k][h] = acc;
    }
    __syncthreads();

    {
        int h = tid >> 5, k = tid & 31;
        int nb = sh_nb[k];
        const uint4* k8 = (const uint4*)(g_kvh + ((size_t)nb * NHEAD + h) * 128);
        const float4* q4 = (const float4*)sh_q[h];
        float dot = 0.f;
        #pragma unroll
        for (int s = 0; s < 8; s++) {
            uint4 kv = __ldg(&k8[s]);
            float4 qa = q4[s * 2], qb = q4[s * 2 + 1];
            float2 f0 = __half22float2(*(__half2*)&kv.x);
            float2 f1 = __half22float2(*(__half2*)&kv.y);
            float2 f2 = __half22float2(*(__half2*)&kv.z);
            float2 f3 = __half22float2(*(__half2*)&kv.w);
            dot += qa.x * f0.x + qa.y * f0.y + qa.z * f1.x + qa.w * f1.y;
            dot += qb.x * f2.x + qb.y * f2.y + qb.z * f3.x + qb.w * f3.y;
        }
        const float4* kg4 = (const float4*)(g_pts + (size_t)nb * PTS_W + h * 72 + 24);
        const float4* qg4 = (const float4*)sh_qg[h];
        float dist = 0.f;
        #pragma unroll
        for (int r = 0; r < 6; r++) {
            float4 kgv = __ldg(&kg4[r]);
            float4 qgv = qg4[r];
            float d0 = qgv.x - kgv.x, d1 = qgv.y - kgv.y;
            float d2 = qgv.z - kgv.z, d3 = qgv.w - kgv.w;
            dist += d0 * d0 + d1 * d1 + d2 * d2 + d3 * d3;
        }
        float logit = 0.57735027f * (0.125f * dot + sh_bias[k][h] - sh_df[h] * dist);
        float m = logit;
        #pragma unroll
        for (int o = 16; o > 0; o >>= 1) m = fmaxf(m, __shfl_xor_sync(0xffffffffu, m, o));
        float e = __expf(logit - m);
        float ssum = e;
        #pragma unroll
        for (int o = 16; o > 0; o >>= 1) ssum += __shfl_xor_sync(0xffffffffu, ssum, o);
        sh_attn[k][h] = e / ssum;
    }
    __syncthreads();

    __half* frow = g_featsh + (size_t)n * FEATS;

    {
        int h = tid >> 5, c4 = tid & 31;
        float4 acc = make_float4(0.f, 0.f, 0.f, 0.f);
        #pragma unroll
        for (int k = 0; k < KNBR; k++) {
            float a = sh_attn[k][h];
            float4 pv = *(const float4*)&sh_pair[k][c4 << 2];
            acc.x += a * pv.x; acc.y += a * pv.y;
            acc.z += a * pv.z; acc.w += a * pv.w;
        }
        __half2 h0 = __floats2half2_rn(acc.x, acc.y);
        __half2 h1 = __floats2half2_rn(acc.z, acc.w);
        uint2 u; u.x = *(uint32_t*)&h0; u.y = *(uint32_t*)&h1;
        ((uint2*)frow)[tid] = u;
    }

    if (tid < 64) {
        int h = tid >> 3, s8 = tid & 7;
        float acc[8];
        #pragma unroll
        for (int j = 0; j < 8; j++) acc[j] = 0.f;
        #pragma unroll
        for (int k = 0; k < KNBR; k++) {
            float a = sh_attn[k][h];
            uint4 vv = __ldg((const uint4*)(g_kvh + ((size_t)sh_nb[k] * NHEAD + h) * 128
                                            + 64 + s8 * 8));
            float2 f0 = __half22float2(*(__half2*)&vv.x);
            float2 f1 = __half22float2(*(__half2*)&vv.y);
            float2 f2 = __half22float2(*(__half2*)&vv.z);
            float2 f3 = __half22float2(*(__half2*)&vv.w);
            acc[0] += a * f0.x; acc[1] += a * f0.y;
            acc[2] += a * f1.x; acc[3] += a * f1.y;
            acc[4] += a * f2.x; acc[5] += a * f2.y;
            acc[6] += a * f3.x; acc[7] += a * f3.y;
        }
        __half2 h0 = __floats2half2_rn(acc[0], acc[1]);
        __half2 h1 = __floats2half2_rn(acc[2], acc[3]);
        __half2 h2 = __floats2half2_rn(acc[4], acc[5]);
        __half2 h3 = __floats2half2_rn(acc[6], acc[7]);
        uint4 u; u.x = *(uint32_t*)&h0; u.y = *(uint32_t*)&h1;
        u.z = *(uint32_t*)&h2; u.w = *(uint32_t*)&h3;
        *(uint4*)(frow + 1024 + h * 64 + s8 * 8) = u;
    } else if (tid < 128) {
        int t2 = tid - 64;
        int h = t2 >> 3, p = t2 & 7;
        float o0 = 0.f, o1 = 0.f, o2 = 0.f;
        #pragma unroll
        for (int k = 0; k < KNBR; k++) {
            float a = sh_attn[k][h];
            const __half* vg = g_vgh + (size_t)sh_nb[k] * (NHEAD * 24) + h * 24 + p * 3;
            o0 += a * __half2float(__ldg(&vg[0]));
            o1 += a * __half2float(__ldg(&vg[1]));
            o2 += a * __half2float(__ldg(&vg[2]));
        }
        o0 -= sh_t[0]; o1 -= sh_t[1]; o2 -= sh_t[2];
        float nrm = 0.f;
        #pragma unroll
        for (int i2 = 0; i2 < 3; i2++) {
            float v = sh_R[0 * 3 + i2] * o0 + sh_R[1 * 3 + i2] * o1 + sh_R[2 * 3 + i2] * o2;
            frow[1536 + h * 24 + p * 3 + i2] = __float2half_rn(v);
            nrm += v * v;
        }
        frow[1728 + h * 8 + p] = __float2half_rn(sqrtf(nrm + 1e-8f));
    }
}

// ---------------- launch -----------------------------------------------------
extern "C" void kernel_launch(void* const* d_in, const int* in_sizes, int n_in,
                              void* d_out, int out_size)
{
    const float* local      = (const float*)d_in[0];
    const float* pos        = (const float*)d_in[1];
    const float* pair       = (const float*)d_in[2];
    const int*   neighbours = (const int*)d_in[4];
    const float* ln_s       = (const float*)d_in[9];
    const float* ln_b       = (const float*)d_in[10];
    const float* W_qkv      = (const float*)d_in[11];
    const float* ln_q_s     = (const float*)d_in[12];
    const float* ln_q_b     = (const float*)d_in[13];
    const float* ln_k_s     = (const float*)d_in[14];
    const float* ln_k_b     = (const float*)d_in[15];
    const float* W_pts      = (const float*)d_in[16];
    const float* W_bias     = (const float*)d_in[17];
    const float* gamma      = (const float*)d_in[18];
    const float* W_out      = (const float*)d_in[19];
    const float* b_out      = (const float*)d_in[20];
    float* out = (float*)d_out;

    __half *xh, *xyh, *featsh, *w12h, *woh;
    float *part;
    cudaGetSymbolAddress((void**)&xh, g_xh);
    cudaGetSymbolAddress((void**)&xyh, g_xyh);
    cudaGetSymbolAddress((void**)&featsh, g_featsh);
    cudaGetSymbolAddress((void**)&w12h, g_w12h);
    cudaGetSymbolAddress((void**)&woh, g_woh);
    cudaGetSymbolAddress((void**)&part, g_part);

    static cudaStream_t s2 = nullptr;
    static cudaEvent_t evStart, evW, evG0, evL0, evA0, evG2;
    static bool init = false;
    if (!init) {
        cudaFuncSetAttribute(hgemm128<true>, cudaFuncAttributeMaxDynamicSharedMemorySize,
                             GEMM_SMEM_BYTES);
        cudaFuncSetAttribute(hgemm128<false>, cudaFuncAttributeMaxDynamicSharedMemorySize,
                             GEMM_SMEM_BYTES);
        cudaStreamCreateWithFlags(&s2, cudaStreamNonBlocking);
        cudaEventCreateWithFlags(&evStart, cudaEventDisableTiming);
        cudaEventCreateWithFlags(&evW, cudaEventDisableTiming);
        cudaEventCreateWithFlags(&evG0, cudaEventDisableTiming);
        cudaEventCreateWithFlags(&evL0, cudaEventDisableTiming);
        cudaEventCreateWithFlags(&evA0, cudaEventDisableTiming);
        cudaEventCreateWithFlags(&evG2, cudaEventDisableTiming);
        init = true;
    }

    // fork: stream s2 handles weight conversions concurrently with ln_local
    cudaEventRecord(evStart, 0);
    cudaStreamWaitEvent(s2, evStart, 0);

    tohalf_strided<<<(DMODEL * QKV_W / 4 + 255) / 256, 256, 0, s2>>>(
        W_qkv, w12h, QKV_W, XYW, 0, DMODEL * QKV_W / 4);
    tohalf_strided<<<(DMODEL * PTS_W / 4 + 255) / 256, 256, 0, s2>>>(
        W_pts, w12h, PTS_W, XYW, QKV_W, DMODEL * PTS_W / 4);
    tohalf_kernel<<<(FEATS * DMODEL / 4 + 255) / 256, 256, 0, s2>>>(
        W_out, woh, FEATS * DMODEL / 4);
    cudaEventRecord(evW, s2);

    ln_local_kernel<<<NRES, 192>>>(local, ln_s, ln_b);
    cudaStreamWaitEvent(0, evW, 0);

    // gemm1 in row halves: [qkv|raw] = x @ [W_qkv|W_pts]
    hgemm128<true><<<dim3((XYW + 127) / 128, HALF_N / 128, 1), 128, GEMM_SMEM_BYTES>>>(
        xh, DMODEL, w12h, xyh, 0, XYW, DMODEL);
    cudaEventRecord(evG0, 0);
    hgemm128<true><<<dim3((XYW + 127) / 128, HALF_N / 128, 1), 128, GEMM_SMEM_BYTES>>>(
        xh + (size_t)HALF_N * DMODEL, DMODEL, w12h,
        xyh + (size_t)HALF_N * XYW, 0, XYW, DMODEL);

    // lnqk half0 on s2 (after gemm1 half0), half1 on main (after gemm1 half1)
    cudaStreamWaitEvent(s2, evG0, 0);
    ln_qk_pts_kernel<<<HALF_N, 256, 0, s2>>>(pos, ln_q_s, ln_q_b, ln_k_s, ln_k_b, 0);
    cudaEventRecord(evL0, s2);
    ln_qk_pts_kernel<<<HALF_N, 256>>>(pos, ln_q_s, ln_q_b, ln_k_s, ln_k_b, HALF_N);
    cudaStreamWaitEvent(0, evL0, 0);

    // attn halves on main; gemm2 half0 (+ its reduce) on s2 overlaps attn half1
    attn_kernel<<<HALF_N, 256>>>(pair, neighbours, W_bias, gamma, 0);
    cudaEventRecord(evA0, 0);
    attn_kernel<<<HALF_N, 256>>>(pair, neighbours, W_bias, gamma, HALF_N);

    cudaStreamWaitEvent(s2, evA0, 0);
    hgemm128<false><<<dim3(DMODEL / 128, HALF_N / 128, 2), 128, GEMM_SMEM_BYTES, s2>>>(
        featsh, FEATS, woh, part, (size_t)NRES * DMODEL, DMODEL, FEATS / 2);
    reduce_bias_kernel<<<HALF_N * DMODEL / 4 / 256, 256, 0, s2>>>(b_out, out, 0);
    cudaEventRecord(evG2, s2);

    hgemm128<false><<<dim3(DMODEL / 128, HALF_N / 128, 2), 128, GEMM_SMEM_BYTES>>>(
        featsh + (size_t)HALF_N * FEATS, FEATS, woh,
        part + (size_t)HALF_N * DMODEL, (size_t)NRES * DMODEL, DMODEL, FEATS / 2);
    reduce_bias_kernel<<<HALF_N * DMODEL / 4 / 256, 256>>>(b_out, out,
                                                           HALF_N * DMODEL / 4);
    cudaStreamWaitEvent(0, evG2, 0);
}